// round 1
// baseline (speedup 1.0000x reference)
#include <cuda_runtime.h>
#include <math.h>

#define S_LEN 128
#define B_SZ  64
#define I_DIM 1024
#define H_DIM 1024
#define O_DIM 1024
#define G4    (4 * H_DIM)   // 4096
#define T_OUT 32

// ---------------- scratch (static device globals; no runtime alloc) ----------
__device__ float g_WihT[I_DIM * G4];      // [I][4H]
__device__ float g_WhhT[H_DIM * G4];      // [H][4H]
__device__ float g_WoutT[H_DIM * O_DIM];  // [H][O]
__device__ float g_bias[G4];
__device__ float g_Xg[S_LEN * B_SZ * G4]; // precomputed input gates
__device__ float g_hA[B_SZ * H_DIM];
__device__ float g_hB[B_SZ * H_DIM];
__device__ float g_c[B_SZ * H_DIM];
__device__ float g_logits[B_SZ * O_DIM];

// ---------------- transpose: dst[c][r] = src[r][c] ---------------------------
__global__ void transpose_kernel(float* __restrict__ dst, const float* __restrict__ src,
                                 int rows, int cols) {
    __shared__ float tile[32][33];
    int bx = blockIdx.x * 32, by = blockIdx.y * 32;
    int x = bx + threadIdx.x;   // col in src
    int y = by + threadIdx.y;   // row in src
#pragma unroll
    for (int i = 0; i < 32; i += 8) {
        if (y + i < rows && x < cols)
            tile[threadIdx.y + i][threadIdx.x] = src[(size_t)(y + i) * cols + x];
    }
    __syncthreads();
    int xo = by + threadIdx.x;  // along src rows
    int yo = bx + threadIdx.y;  // along src cols
#pragma unroll
    for (int i = 0; i < 32; i += 8) {
        if (yo + i < cols && xo < rows)
            dst[(size_t)(yo + i) * rows + xo] = tile[threadIdx.x][threadIdx.y + i];
    }
}

// ---------------- bias fold + state init ------------------------------------
__global__ void prep_state_kernel(const float* __restrict__ h0, const float* __restrict__ c0,
                                  const float* __restrict__ b_ih, const float* __restrict__ b_hh) {
    int i = blockIdx.x * blockDim.x + threadIdx.x;
    if (i < G4) g_bias[i] = b_ih[i] + b_hh[i];
    if (i < B_SZ * H_DIM) { g_hA[i] = h0[i]; g_c[i] = c0[i]; }
}

// ---------------- big SGEMM: C[M,N] = A[M,K] * B[K,N] (row-major) ------------
// BM=128, BN=64, BK=16, 256 threads, 8x4 micro-tile. M%128==0, N%64==0, K%16==0.
#define GBM 128
#define GBN 64
#define GBK 16
__global__ __launch_bounds__(256) void sgemm_kernel(const float* __restrict__ A,
                                                    const float* __restrict__ B,
                                                    float* __restrict__ C,
                                                    int M, int N, int K) {
    __shared__ float As[GBK][GBM + 4];  // pad keeps 16B alignment (132*4 % 16 == 0)
    __shared__ float Bs[GBK][GBN];
    int tid = threadIdx.x;
    int row0 = blockIdx.y * GBM;
    int col0 = blockIdx.x * GBN;
    int tx = tid & 15;   // N dir, 4 cols each
    int ty = tid >> 4;   // M dir, 8 rows each
    float acc[8][4] = {};
    for (int k0 = 0; k0 < K; k0 += GBK) {
#pragma unroll
        for (int i = 0; i < 8; ++i) {
            int idx = tid + i * 256;      // 0..2047
            int m = idx >> 4, kk = idx & 15;
            As[kk][m] = A[(size_t)(row0 + m) * K + k0 + kk];
        }
#pragma unroll
        for (int i = 0; i < 4; ++i) {
            int idx = tid + i * 256;      // 0..1023
            int kk = idx >> 6, n = idx & 63;
            Bs[kk][n] = B[(size_t)(k0 + kk) * N + col0 + n];
        }
        __syncthreads();
#pragma unroll
        for (int kk = 0; kk < GBK; ++kk) {
            float4 a01 = *(const float4*)&As[kk][ty * 8];
            float4 a23 = *(const float4*)&As[kk][ty * 8 + 4];
            float4 b   = *(const float4*)&Bs[kk][tx * 4];
            float a[8] = {a01.x, a01.y, a01.z, a01.w, a23.x, a23.y, a23.z, a23.w};
            float bb[4] = {b.x, b.y, b.z, b.w};
#pragma unroll
            for (int i = 0; i < 8; ++i)
#pragma unroll
                for (int j = 0; j < 4; ++j)
                    acc[i][j] += a[i] * bb[j];
        }
        __syncthreads();
    }
#pragma unroll
    for (int i = 0; i < 8; ++i) {
        float4 v = make_float4(acc[i][0], acc[i][1], acc[i][2], acc[i][3]);
        *(float4*)&C[(size_t)(row0 + ty * 8 + i) * N + col0 + tx * 4] = v;
    }
}

// ---------------- fused LSTM cell step ---------------------------------------
// grid = 128 blocks; block b owns h-slice j0 = b*8 and computes the 64x32 gate
// tile (4 gates x 8 j's for all 64 batch rows), then applies the cell update.
#define CBK 16
__device__ __forceinline__ void cell_gemm_accum(const float* __restrict__ vec,  // [64][1024]
                                                const float* __restrict__ W,    // [1024][4096]
                                                int j0, int tid, int tx, int ty,
                                                float acc[2][4],
                                                float (*As)[66], float (*Bs)[32]) {
    for (int k0 = 0; k0 < 1024; k0 += CBK) {
#pragma unroll
        for (int i = 0; i < 4; ++i) {
            int idx = tid + i * 256;     // 0..1023 -> 64x16
            int m = idx >> 4, kk = idx & 15;
            As[kk][m] = vec[m * 1024 + k0 + kk];
        }
#pragma unroll
        for (int i = 0; i < 2; ++i) {
            int idx = tid + i * 256;     // 0..511 -> 16x32
            int kk = idx >> 5, c = idx & 31;
            int w = (c >> 3) * H_DIM + j0 + (c & 7);
            Bs[kk][c] = W[(size_t)(k0 + kk) * G4 + w];
        }
        __syncthreads();
#pragma unroll
        for (int kk = 0; kk < CBK; ++kk) {
            float2 a = *(const float2*)&As[kk][ty * 2];
            float4 b = *(const float4*)&Bs[kk][tx * 4];
            acc[0][0] += a.x * b.x; acc[0][1] += a.x * b.y;
            acc[0][2] += a.x * b.z; acc[0][3] += a.x * b.w;
            acc[1][0] += a.y * b.x; acc[1][1] += a.y * b.y;
            acc[1][2] += a.y * b.z; acc[1][3] += a.y * b.w;
        }
        __syncthreads();
    }
}

__global__ __launch_bounds__(256) void lstm_cell_kernel(const float* __restrict__ h_in,
                                                        float* __restrict__ h_out,
                                                        float* __restrict__ c_io,
                                                        const float* __restrict__ xg_row,  // [B][4H] or null
                                                        const float* __restrict__ x_row) { // [B][O]  or null
    __shared__ float As[CBK][66];
    __shared__ float Bs[CBK][32];
    __shared__ float Gs[64][33];
    int tid = threadIdx.x;
    int j0 = blockIdx.x * 8;
    int tx = tid & 7;    // cols tx*4..+3
    int ty = tid >> 3;   // rows ty*2, ty*2+1
    float acc[2][4] = {};

    cell_gemm_accum(h_in, g_WhhT, j0, tid, tx, ty, acc, As, Bs);
    if (x_row) cell_gemm_accum(x_row, g_WihT, j0, tid, tx, ty, acc, As, Bs);

#pragma unroll
    for (int i = 0; i < 2; ++i) {
        int m = ty * 2 + i;
#pragma unroll
        for (int j = 0; j < 4; ++j) {
            int c = tx * 4 + j;
            int w = (c >> 3) * H_DIM + j0 + (c & 7);
            float v = acc[i][j] + g_bias[w];
            if (xg_row) v += xg_row[m * G4 + w];
            Gs[m][c] = v;
        }
    }
    __syncthreads();
#pragma unroll
    for (int p = 0; p < 2; ++p) {
        int idx = tid + p * 256;          // 0..511 -> (m, jj)
        int m = idx >> 3, jj = idx & 7;
        float gi = Gs[m][jj];
        float gf = Gs[m][8 + jj];
        float gg = Gs[m][16 + jj];
        float go = Gs[m][24 + jj];
        int off = m * H_DIM + j0 + jj;
        float cold = c_io[off];
        float si = 1.f / (1.f + expf(-gi));
        float sf = 1.f / (1.f + expf(-gf));
        float so = 1.f / (1.f + expf(-go));
        float cn = sf * cold + si * tanhf(gg);
        c_io[off] = cn;
        h_out[off] = so * tanhf(cn);
    }
}

// ---------------- projection GEMM: logits = h @ WoutT + b_out ----------------
// grid (O/32, B/16) = (32, 4), 256 threads, each thread 2 outputs.
__global__ __launch_bounds__(256) void proj_gemm_kernel(const float* __restrict__ h,
                                                        const float* __restrict__ b_out) {
    __shared__ float As[16][18];
    __shared__ float Bs[16][32];
    int tid = threadIdx.x;
    int col0 = blockIdx.x * 32;
    int row0 = blockIdx.y * 16;
    int tx = tid & 31;
    int ty = tid >> 5;   // 0..7 -> rows ty*2, ty*2+1
    float acc0 = 0.f, acc1 = 0.f;
    for (int k0 = 0; k0 < H_DIM; k0 += 16) {
        {
            int m = tid >> 4, kk = tid & 15;  // 256 = 16x16
            As[kk][m] = h[(row0 + m) * H_DIM + k0 + kk];
        }
#pragma unroll
        for (int i = 0; i < 2; ++i) {
            int idx = tid + i * 256;
            int kk = idx >> 5, n = idx & 31;
            Bs[kk][n] = g_WoutT[(size_t)(k0 + kk) * O_DIM + col0 + n];
        }
        __syncthreads();
#pragma unroll
        for (int kk = 0; kk < 16; ++kk) {
            float b = Bs[kk][tx];
            float2 a = *(const float2*)&As[kk][ty * 2];
            acc0 += a.x * b;
            acc1 += a.y * b;
        }
        __syncthreads();
    }
    float bb = b_out[col0 + tx];
    g_logits[(row0 + ty * 2)     * O_DIM + col0 + tx] = acc0 + bb;
    g_logits[(row0 + ty * 2 + 1) * O_DIM + col0 + tx] = acc1 + bb;
}

// ---------------- log-softmax per row, writes into d_out slice ---------------
__global__ __launch_bounds__(256) void logsoftmax_kernel(float* __restrict__ dst) {
    int b = blockIdx.x;
    const float* row = g_logits + b * O_DIM;
    __shared__ float redmax[8];
    __shared__ float redsum[8];
    __shared__ float s_lse;
    int tid = threadIdx.x;

    float m = -1e30f;
    for (int o = tid; o < O_DIM; o += 256) m = fmaxf(m, row[o]);
#pragma unroll
    for (int s = 16; s; s >>= 1) m = fmaxf(m, __shfl_xor_sync(0xffffffffu, m, s));
    if ((tid & 31) == 0) redmax[tid >> 5] = m;
    __syncthreads();
    if (tid == 0) {
        float mm = redmax[0];
#pragma unroll
        for (int i = 1; i < 8; ++i) mm = fmaxf(mm, redmax[i]);
        redmax[0] = mm;
    }
    __syncthreads();
    float mm = redmax[0];

    float s = 0.f;
    for (int o = tid; o < O_DIM; o += 256) s += expf(row[o] - mm);
#pragma unroll
    for (int sh = 16; sh; sh >>= 1) s += __shfl_xor_sync(0xffffffffu, s, sh);
    if ((tid & 31) == 0) redsum[tid >> 5] = s;
    __syncthreads();
    if (tid == 0) {
        float tot = 0.f;
#pragma unroll
        for (int i = 0; i < 8; ++i) tot += redsum[i];
        s_lse = mm + logf(tot);
    }
    __syncthreads();
    float lse = s_lse;
    for (int o = tid; o < O_DIM; o += 256) dst[b * O_DIM + o] = row[o] - lse;
}

// ---------------- final h,c copy --------------------------------------------
__global__ void copy_hc_kernel(const float* __restrict__ h_fin, float* __restrict__ out) {
    int i = blockIdx.x * blockDim.x + threadIdx.x;
    if (i < B_SZ * H_DIM) {
        out[i] = h_fin[i];
        out[B_SZ * H_DIM + i] = g_c[i];
    }
}

// ---------------- host orchestration -----------------------------------------
extern "C" void kernel_launch(void* const* d_in, const int* in_sizes, int n_in,
                              void* d_out, int out_size) {
    const float* input = (const float*)d_in[0];
    const float* h0    = (const float*)d_in[1];
    const float* c0    = (const float*)d_in[2];
    const float* W_ih  = (const float*)d_in[3];
    const float* W_hh  = (const float*)d_in[4];
    const float* b_ih  = (const float*)d_in[5];
    const float* b_hh  = (const float*)d_in[6];
    const float* W_out = (const float*)d_in[7];
    const float* b_out = (const float*)d_in[8];
    float* out = (float*)d_out;

    float *p_WihT, *p_WhhT, *p_WoutT, *p_Xg, *p_hA, *p_hB, *p_c;
    cudaGetSymbolAddress((void**)&p_WihT, g_WihT);
    cudaGetSymbolAddress((void**)&p_WhhT, g_WhhT);
    cudaGetSymbolAddress((void**)&p_WoutT, g_WoutT);
    cudaGetSymbolAddress((void**)&p_Xg, g_Xg);
    cudaGetSymbolAddress((void**)&p_hA, g_hA);
    cudaGetSymbolAddress((void**)&p_hB, g_hB);
    cudaGetSymbolAddress((void**)&p_c, g_c);

    dim3 tb(32, 8);
    transpose_kernel<<<dim3(I_DIM / 32, G4 / 32), tb>>>(p_WihT, W_ih, G4, I_DIM);
    transpose_kernel<<<dim3(H_DIM / 32, G4 / 32), tb>>>(p_WhhT, W_hh, G4, H_DIM);
    transpose_kernel<<<dim3(H_DIM / 32, O_DIM / 32), tb>>>(p_WoutT, W_out, O_DIM, H_DIM);
    prep_state_kernel<<<(B_SZ * H_DIM + 255) / 256, 256>>>(h0, c0, b_ih, b_hh);

    // Xg[(t,b), 4H] = input @ WihT
    sgemm_kernel<<<dim3(G4 / GBN, (S_LEN * B_SZ) / GBM), 256>>>(
        input, p_WihT, p_Xg, S_LEN * B_SZ, G4, I_DIM);

    float* hbuf[2] = {p_hA, p_hB};

    // encode: 128 steps (xg precomputed, no x GEMM)
    for (int t = 0; t < S_LEN; ++t) {
        lstm_cell_kernel<<<H_DIM / 8, 256>>>(hbuf[t & 1], hbuf[(t + 1) & 1], p_c,
                                             p_Xg + (size_t)t * B_SZ * G4, (const float*)nullptr);
    }
    // h now in hbuf[0]
    proj_gemm_kernel<<<dim3(O_DIM / 32, B_SZ / 16), 256>>>(hbuf[0], b_out);
    logsoftmax_kernel<<<B_SZ, 256>>>(out + 0);

    // autoregressive decode: 31 steps, x = previous output slice of d_out
    for (int d = 1; d < T_OUT; ++d) {
        int s = S_LEN + (d - 1);  // global step parity
        const float* x_prev = out + (size_t)(d - 1) * B_SZ * O_DIM;
        lstm_cell_kernel<<<H_DIM / 8, 256>>>(hbuf[s & 1], hbuf[(s + 1) & 1], p_c,
                                             (const float*)nullptr, x_prev);
        proj_gemm_kernel<<<dim3(O_DIM / 32, B_SZ / 16), 256>>>(hbuf[(s + 1) & 1], b_out);
        logsoftmax_kernel<<<B_SZ, 256>>>(out + (size_t)d * B_SZ * O_DIM);
    }

    // final h is in hbuf[(128+31) & 1] == hbuf[1]
    copy_hc_kernel<<<(B_SZ * H_DIM + 255) / 256, 256>>>(
        hbuf[(S_LEN + T_OUT - 1) & 1], out + (size_t)T_OUT * B_SZ * O_DIM);
}

// round 7
// speedup vs baseline: 1.0282x; 1.0282x over previous
#include <cuda_runtime.h>
#include <math.h>
#include <stdint.h>

#define S_LEN 128
#define B_SZ  64
#define I_DIM 1024
#define H_DIM 1024
#define O_DIM 1024
#define G4    (4 * H_DIM)   // 4096
#define T_OUT 32

// ---------------- scratch (static device globals; no runtime alloc) ----------
__device__ float g_WihT[I_DIM * G4];       // [I][4H]  hi part (tf32)
__device__ float g_WihT_lo[I_DIM * G4];    //          lo part (tf32 residual)
__device__ float g_WhhT[H_DIM * G4];
__device__ float g_WhhT_lo[H_DIM * G4];
__device__ float g_WoutT[H_DIM * O_DIM];
__device__ float g_WoutT_lo[H_DIM * O_DIM];
__device__ float g_bias[G4];
__device__ float g_Xg[S_LEN * B_SZ * G4];  // precomputed input gates (fp32)
__device__ float g_hA[B_SZ * H_DIM];
__device__ float g_hB[B_SZ * H_DIM];
__device__ float g_c[B_SZ * H_DIM];
__device__ float g_pp[4][B_SZ][O_DIM];     // split-K proj partials

// ---------------- tf32 helpers ------------------------------------------------
__device__ __forceinline__ uint32_t f2tf32(float f) {
    uint32_t u;
    asm("cvt.rna.tf32.f32 %0, %1;" : "=r"(u) : "f"(f));
    return u;
}
__device__ __forceinline__ void split_tf32(float v, uint32_t& hi, uint32_t& lo) {
    hi = f2tf32(v);
    lo = f2tf32(v - __uint_as_float(hi));
}

__device__ __forceinline__ void mma8(float c[4],
                                     uint32_t a0, uint32_t a1, uint32_t a2, uint32_t a3,
                                     uint32_t b0, uint32_t b1) {
    asm volatile(
        "mma.sync.aligned.m16n8k8.row.col.f32.tf32.tf32.f32 "
        "{%0,%1,%2,%3}, {%4,%5,%6,%7}, {%8,%9}, {%0,%1,%2,%3};"
        : "+f"(c[0]), "+f"(c[1]), "+f"(c[2]), "+f"(c[3])
        : "r"(a0), "r"(a1), "r"(a2), "r"(a3), "r"(b0), "r"(b1));
}

// 3xTF32 compound: acc += a_lo*b_hi + a_hi*b_lo + a_hi*b_hi
__device__ __forceinline__ void mma3(float c[4],
                                     const uint32_t ah[4], const uint32_t al[4],
                                     uint32_t bh0, uint32_t bh1,
                                     uint32_t bl0, uint32_t bl1) {
    mma8(c, al[0], al[1], al[2], al[3], bh0, bh1);
    mma8(c, ah[0], ah[1], ah[2], ah[3], bl0, bl1);
    mma8(c, ah[0], ah[1], ah[2], ah[3], bh0, bh1);
}

// ---------------- transpose + tf32 hi/lo split: dst[c][r] = src[r][c] --------
__global__ void transpose_split_kernel(float* __restrict__ dst_hi,
                                       float* __restrict__ dst_lo,
                                       const float* __restrict__ src,
                                       int rows, int cols) {
    __shared__ float tile[32][33];
    int bx = blockIdx.x * 32, by = blockIdx.y * 32;
    int x = bx + threadIdx.x;
    int y = by + threadIdx.y;
#pragma unroll
    for (int i = 0; i < 32; i += 8) {
        if (y + i < rows && x < cols)
            tile[threadIdx.y + i][threadIdx.x] = src[(size_t)(y + i) * cols + x];
    }
    __syncthreads();
    int xo = by + threadIdx.x;
    int yo = bx + threadIdx.y;
#pragma unroll
    for (int i = 0; i < 32; i += 8) {
        if (yo + i < cols && xo < rows) {
            float v = tile[threadIdx.x][threadIdx.y + i];
            uint32_t hi, lo;
            split_tf32(v, hi, lo);
            size_t o = (size_t)(yo + i) * rows + xo;
            dst_hi[o] = __uint_as_float(hi);
            dst_lo[o] = __uint_as_float(lo);
        }
    }
}

// ---------------- bias fold + state init ------------------------------------
__global__ void prep_state_kernel(const float* __restrict__ h0, const float* __restrict__ c0,
                                  const float* __restrict__ b_ih, const float* __restrict__ b_hh) {
    int i = blockIdx.x * blockDim.x + threadIdx.x;
    if (i < G4) g_bias[i] = b_ih[i] + b_hh[i];
    if (i < B_SZ * H_DIM) { g_hA[i] = h0[i]; g_c[i] = c0[i]; }
}

// ---------------- big input GEMM (3xTF32): Xg = input @ WihT ------------------
// C[8192,4096], tile 64x64, K-chunk 32, 8 warps (4 m x 2 n), warp = m16 x n32.
__global__ __launch_bounds__(256) void gemm_xg_mma(const float* __restrict__ A) {
    __shared__ uint32_t Ah[64][36], Al[64][36];   // [m][k]
    __shared__ uint32_t Bh[32][68], Bl[32][68];   // [k][n]
    int tid = threadIdx.x, wid = tid >> 5, lane = tid & 31;
    int row0 = blockIdx.y * 64, col0 = blockIdx.x * 64;
    int m0 = (wid & 3) * 16;
    int n0 = (wid >> 2) * 32;
    int gq = lane >> 2, tq = lane & 3;
    float acc[4][4] = {};
    for (int k0 = 0; k0 < 1024; k0 += 32) {
#pragma unroll
        for (int i = 0; i < 2; ++i) {
            int idx = tid + i * 256;            // 512 float4 = 64x32 floats
            int m = idx >> 3, k4 = (idx & 7) * 4;
            float4 v = *(const float4*)&A[(size_t)(row0 + m) * 1024 + k0 + k4];
            split_tf32(v.x, Ah[m][k4 + 0], Al[m][k4 + 0]);
            split_tf32(v.y, Ah[m][k4 + 1], Al[m][k4 + 1]);
            split_tf32(v.z, Ah[m][k4 + 2], Al[m][k4 + 2]);
            split_tf32(v.w, Ah[m][k4 + 3], Al[m][k4 + 3]);
        }
#pragma unroll
        for (int i = 0; i < 8; ++i) {
            int idx = tid + i * 256;            // 32k x 64n
            int k = idx >> 6, n = idx & 63;
            size_t o = (size_t)(k0 + k) * G4 + col0 + n;
            Bh[k][n] = __float_as_uint(g_WihT[o]);
            Bl[k][n] = __float_as_uint(g_WihT_lo[o]);
        }
        __syncthreads();
#pragma unroll
        for (int k8 = 0; k8 < 4; ++k8) {
            int kk = k8 * 8;
            uint32_t ah[4], al[4];
            ah[0] = Ah[m0 + gq][kk + tq];     ah[1] = Ah[m0 + gq + 8][kk + tq];
            ah[2] = Ah[m0 + gq][kk + tq + 4]; ah[3] = Ah[m0 + gq + 8][kk + tq + 4];
            al[0] = Al[m0 + gq][kk + tq];     al[1] = Al[m0 + gq + 8][kk + tq];
            al[2] = Al[m0 + gq][kk + tq + 4]; al[3] = Al[m0 + gq + 8][kk + tq + 4];
#pragma unroll
            for (int na = 0; na < 4; ++na) {
                int nc = n0 + na * 8 + gq;
                uint32_t bh0 = Bh[kk + tq][nc],     bh1 = Bh[kk + tq + 4][nc];
                uint32_t bl0 = Bl[kk + tq][nc],     bl1 = Bl[kk + tq + 4][nc];
                mma3(acc[na], ah, al, bh0, bh1, bl0, bl1);
            }
        }
        __syncthreads();
    }
#pragma unroll
    for (int na = 0; na < 4; ++na) {
        int r = row0 + m0 + gq;
        int cc = col0 + n0 + na * 8 + 2 * tq;
        *(float2*)&g_Xg[(size_t)r * G4 + cc]       = make_float2(acc[na][0], acc[na][1]);
        *(float2*)&g_Xg[(size_t)(r + 8) * G4 + cc] = make_float2(acc[na][2], acc[na][3]);
    }
}

// ---------------- fused LSTM cell step (3xTF32) -------------------------------
// 128 blocks; block b owns j0=b*8, computes 64x32 gate tile, fuses cell update.
__global__ __launch_bounds__(256) void lstm_cell_mma(const float* __restrict__ h_in,
                                                     float* __restrict__ h_out,
                                                     float* __restrict__ c_io,
                                                     const float* __restrict__ xg_row,
                                                     const float* __restrict__ x_row) {
    __shared__ uint32_t Ah[64][36], Al[64][36];   // [m][k], K-chunk 32
    __shared__ uint32_t Bh[32][36], Bl[32][36];   // [k][c]
    __shared__ float Gs[64][33];
    int tid = threadIdx.x, wid = tid >> 5, lane = tid & 31;
    int j0 = blockIdx.x * 8;
    int m0 = (wid & 3) * 16;
    int nb = (wid >> 2) * 2;
    int gq = lane >> 2, tq = lane & 3;
    float acc[2][4] = {};

    const float* Avec[2]; const float* Wh[2]; const float* Wl[2];
    int npass = 1;
    Avec[0] = h_in; Wh[0] = g_WhhT; Wl[0] = g_WhhT_lo;
    if (x_row) { Avec[1] = x_row; Wh[1] = g_WihT; Wl[1] = g_WihT_lo; npass = 2; }

    for (int p = 0; p < npass; ++p) {
        const float* V = Avec[p];
        const float* WH = Wh[p];
        const float* WL = Wl[p];
        for (int k0 = 0; k0 < 1024; k0 += 32) {
#pragma unroll
            for (int i = 0; i < 2; ++i) {
                int idx = tid + i * 256;        // 512 float4 = 64x32
                int m = idx >> 3, k4 = (idx & 7) * 4;
                float4 v = *(const float4*)&V[m * 1024 + k0 + k4];
                split_tf32(v.x, Ah[m][k4 + 0], Al[m][k4 + 0]);
                split_tf32(v.y, Ah[m][k4 + 1], Al[m][k4 + 1]);
                split_tf32(v.z, Ah[m][k4 + 2], Al[m][k4 + 2]);
                split_tf32(v.w, Ah[m][k4 + 3], Al[m][k4 + 3]);
            }
#pragma unroll
            for (int i = 0; i < 4; ++i) {
                int idx = tid + i * 256;        // 32k x 32c
                int k = idx >> 5, c = idx & 31;
                size_t o = (size_t)(k0 + k) * G4 + (c >> 3) * H_DIM + j0 + (c & 7);
                Bh[k][c] = __float_as_uint(WH[o]);
                Bl[k][c] = __float_as_uint(WL[o]);
            }
            __syncthreads();
#pragma unroll
            for (int k8 = 0; k8 < 4; ++k8) {
                int kk = k8 * 8;
                uint32_t ah[4], al[4];
                ah[0] = Ah[m0 + gq][kk + tq];     ah[1] = Ah[m0 + gq + 8][kk + tq];
                ah[2] = Ah[m0 + gq][kk + tq + 4]; ah[3] = Ah[m0 + gq + 8][kk + tq + 4];
                al[0] = Al[m0 + gq][kk + tq];     al[1] = Al[m0 + gq + 8][kk + tq];
                al[2] = Al[m0 + gq][kk + tq + 4]; al[3] = Al[m0 + gq + 8][kk + tq + 4];
#pragma unroll
                for (int na = 0; na < 2; ++na) {
                    int nc = (nb + na) * 8 + gq;
                    uint32_t bh0 = Bh[kk + tq][nc],     bh1 = Bh[kk + tq + 4][nc];
                    uint32_t bl0 = Bl[kk + tq][nc],     bl1 = Bl[kk + tq + 4][nc];
                    mma3(acc[na], ah, al, bh0, bh1, bl0, bl1);
                }
            }
            __syncthreads();
        }
    }

#pragma unroll
    for (int na = 0; na < 2; ++na) {
        int col = (nb + na) * 8 + 2 * tq;
        Gs[m0 + gq][col]         = acc[na][0];
        Gs[m0 + gq][col + 1]     = acc[na][1];
        Gs[m0 + gq + 8][col]     = acc[na][2];
        Gs[m0 + gq + 8][col + 1] = acc[na][3];
    }
    __syncthreads();
#pragma unroll
    for (int p = 0; p < 2; ++p) {
        int idx = tid + p * 256;
        int m = idx >> 3, jj = idx & 7;
        float gi = Gs[m][jj]      + g_bias[0 * H_DIM + j0 + jj];
        float gf = Gs[m][8 + jj]  + g_bias[1 * H_DIM + j0 + jj];
        float gg = Gs[m][16 + jj] + g_bias[2 * H_DIM + j0 + jj];
        float go = Gs[m][24 + jj] + g_bias[3 * H_DIM + j0 + jj];
        if (xg_row) {
            gi += xg_row[m * G4 + 0 * H_DIM + j0 + jj];
            gf += xg_row[m * G4 + 1 * H_DIM + j0 + jj];
            gg += xg_row[m * G4 + 2 * H_DIM + j0 + jj];
            go += xg_row[m * G4 + 3 * H_DIM + j0 + jj];
        }
        int off = m * H_DIM + j0 + jj;
        float cold = c_io[off];
        float si = 1.f / (1.f + expf(-gi));
        float sf = 1.f / (1.f + expf(-gf));
        float so = 1.f / (1.f + expf(-go));
        float cn = sf * cold + si * tanhf(gg);
        c_io[off] = cn;
        h_out[off] = so * tanhf(cn);
    }
}

// ---------------- projection GEMM (3xTF32, split-K=4) -------------------------
__global__ __launch_bounds__(256) void proj_mma(const float* __restrict__ h) {
    __shared__ uint32_t Ah[64][36], Al[64][36];
    __shared__ uint32_t Bh[32][36], Bl[32][36];
    int tid = threadIdx.x, wid = tid >> 5, lane = tid & 31;
    int col0 = blockIdx.x * 32;
    int ks = blockIdx.y;
    int kbase = ks * 256;
    int m0 = (wid & 3) * 16;
    int nb = (wid >> 2) * 2;
    int gq = lane >> 2, tq = lane & 3;
    float acc[2][4] = {};
    for (int k0 = 0; k0 < 256; k0 += 32) {
#pragma unroll
        for (int i = 0; i < 2; ++i) {
            int idx = tid + i * 256;
            int m = idx >> 3, k4 = (idx & 7) * 4;
            float4 v = *(const float4*)&h[m * 1024 + kbase + k0 + k4];
            split_tf32(v.x, Ah[m][k4 + 0], Al[m][k4 + 0]);
            split_tf32(v.y, Ah[m][k4 + 1], Al[m][k4 + 1]);
            split_tf32(v.z, Ah[m][k4 + 2], Al[m][k4 + 2]);
            split_tf32(v.w, Ah[m][k4 + 3], Al[m][k4 + 3]);
        }
#pragma unroll
        for (int i = 0; i < 4; ++i) {
            int idx = tid + i * 256;
            int k = idx >> 5, n = idx & 31;
            size_t o = (size_t)(kbase + k0 + k) * O_DIM + col0 + n;
            Bh[k][n] = __float_as_uint(g_WoutT[o]);
            Bl[k][n] = __float_as_uint(g_WoutT_lo[o]);
        }
        __syncthreads();
#pragma unroll
        for (int k8 = 0; k8 < 4; ++k8) {
            int kk = k8 * 8;
            uint32_t ah[4], al[4];
            ah[0] = Ah[m0 + gq][kk + tq];     ah[1] = Ah[m0 + gq + 8][kk + tq];
            ah[2] = Ah[m0 + gq][kk + tq + 4]; ah[3] = Ah[m0 + gq + 8][kk + tq + 4];
            al[0] = Al[m0 + gq][kk + tq];     al[1] = Al[m0 + gq + 8][kk + tq];
            al[2] = Al[m0 + gq][kk + tq + 4]; al[3] = Al[m0 + gq + 8][kk + tq + 4];
#pragma unroll
            for (int na = 0; na < 2; ++na) {
                int nc = (nb + na) * 8 + gq;
                uint32_t bh0 = Bh[kk + tq][nc],     bh1 = Bh[kk + tq + 4][nc];
                uint32_t bl0 = Bl[kk + tq][nc],     bl1 = Bl[kk + tq + 4][nc];
                mma3(acc[na], ah, al, bh0, bh1, bl0, bl1);
            }
        }
        __syncthreads();
    }
#pragma unroll
    for (int na = 0; na < 2; ++na) {
        int cc = col0 + (nb + na) * 8 + 2 * tq;
        int r = m0 + gq;
        *(float2*)&g_pp[ks][r][cc]     = make_float2(acc[na][0], acc[na][1]);
        *(float2*)&g_pp[ks][r + 8][cc] = make_float2(acc[na][2], acc[na][3]);
    }
}

// ---------------- log-softmax per row (reduces split-K partials + bias) ------
__global__ __launch_bounds__(256) void logsoftmax_kernel(float* __restrict__ dst,
                                                         const float* __restrict__ b_out) {
    __shared__ float row[O_DIM];
    __shared__ float red[8];
    __shared__ float s_lse;
    int b = blockIdx.x;
    int tid = threadIdx.x;

    float lm = -1e30f;
    for (int o = tid; o < O_DIM; o += 256) {
        float v = g_pp[0][b][o] + g_pp[1][b][o] + g_pp[2][b][o] + g_pp[3][b][o]
                + b_out[o];
        row[o] = v;
        lm = fmaxf(lm, v);
    }
#pragma unroll
    for (int s = 16; s; s >>= 1) lm = fmaxf(lm, __shfl_xor_sync(0xffffffffu, lm, s));
    if ((tid & 31) == 0) red[tid >> 5] = lm;
    __syncthreads();
    if (tid == 0) {
        float mm = red[0];
#pragma unroll
        for (int i = 1; i < 8; ++i) mm = fmaxf(mm, red[i]);
        red[0] = mm;
    }
    __syncthreads();
    float mm = red[0];

    float s = 0.f;
    for (int o = tid; o < O_DIM; o += 256) s += expf(row[o] - mm);
#pragma unroll
    for (int sh = 16; sh; sh >>= 1) s += __shfl_xor_sync(0xffffffffu, s, sh);
    if ((tid & 31) == 0) red[tid >> 5] = s;
    __syncthreads();
    if (tid == 0) {
        float tot = 0.f;
#pragma unroll
        for (int i = 0; i < 8; ++i) tot += red[i];
        s_lse = mm + logf(tot);
    }
    __syncthreads();
    float lse = s_lse;
    for (int o = tid; o < O_DIM; o += 256) dst[b * O_DIM + o] = row[o] - lse;
}

// ---------------- final h,c copy --------------------------------------------
__global__ void copy_hc_kernel(const float* __restrict__ h_fin, float* __restrict__ out) {
    int i = blockIdx.x * blockDim.x + threadIdx.x;
    if (i < B_SZ * H_DIM) {
        out[i] = h_fin[i];
        out[B_SZ * H_DIM + i] = g_c[i];
    }
}

// ---------------- host orchestration -----------------------------------------
extern "C" void kernel_launch(void* const* d_in, const int* in_sizes, int n_in,
                              void* d_out, int out_size) {
    const float* input = (const float*)d_in[0];
    const float* h0    = (const float*)d_in[1];
    const float* c0    = (const float*)d_in[2];
    const float* W_ih  = (const float*)d_in[3];
    const float* W_hh  = (const float*)d_in[4];
    const float* b_ih  = (const float*)d_in[5];
    const float* b_hh  = (const float*)d_in[6];
    const float* W_out = (const float*)d_in[7];
    const float* b_out = (const float*)d_in[8];
    float* out = (float*)d_out;

    float *p_WihT, *p_WihT_lo, *p_WhhT, *p_WhhT_lo, *p_WoutT, *p_WoutT_lo;
    float *p_Xg, *p_hA, *p_hB, *p_c;
    cudaGetSymbolAddress((void**)&p_WihT, g_WihT);
    cudaGetSymbolAddress((void**)&p_WihT_lo, g_WihT_lo);
    cudaGetSymbolAddress((void**)&p_WhhT, g_WhhT);
    cudaGetSymbolAddress((void**)&p_WhhT_lo, g_WhhT_lo);
    cudaGetSymbolAddress((void**)&p_WoutT, g_WoutT);
    cudaGetSymbolAddress((void**)&p_WoutT_lo, g_WoutT_lo);
    cudaGetSymbolAddress((void**)&p_Xg, g_Xg);
    cudaGetSymbolAddress((void**)&p_hA, g_hA);
    cudaGetSymbolAddress((void**)&p_hB, g_hB);
    cudaGetSymbolAddress((void**)&p_c, g_c);

    dim3 tb(32, 8);
    transpose_split_kernel<<<dim3(I_DIM / 32, G4 / 32), tb>>>(p_WihT, p_WihT_lo, W_ih, G4, I_DIM);
    transpose_split_kernel<<<dim3(H_DIM / 32, G4 / 32), tb>>>(p_WhhT, p_WhhT_lo, W_hh, G4, H_DIM);
    transpose_split_kernel<<<dim3(H_DIM / 32, O_DIM / 32), tb>>>(p_WoutT, p_WoutT_lo, W_out, O_DIM, H_DIM);
    prep_state_kernel<<<(B_SZ * H_DIM + 255) / 256, 256>>>(h0, c0, b_ih, b_hh);

    // Xg[(t,b), 4H] = input @ WihT  (3xTF32 mma)
    gemm_xg_mma<<<dim3(G4 / 64, (S_LEN * B_SZ) / 64), 256>>>(input);

    float* hbuf[2] = {p_hA, p_hB};

    // encode: 128 steps (xg precomputed, no x-side GEMM)
    for (int t = 0; t < S_LEN; ++t) {
        lstm_cell_mma<<<H_DIM / 8, 256>>>(hbuf[t & 1], hbuf[(t + 1) & 1], p_c,
                                          p_Xg + (size_t)t * B_SZ * G4,
                                          (const float*)nullptr);
    }
    // h now in hbuf[0]
    proj_mma<<<dim3(O_DIM / 32, 4), 256>>>(hbuf[0]);
    logsoftmax_kernel<<<B_SZ, 256>>>(out + 0, b_out);

    // autoregressive decode: 31 steps, x = previous output slice of d_out
    for (int d = 1; d < T_OUT; ++d) {
        int s = S_LEN + (d - 1);
        const float* x_prev = out + (size_t)(d - 1) * B_SZ * O_DIM;
        lstm_cell_mma<<<H_DIM / 8, 256>>>(hbuf[s & 1], hbuf[(s + 1) & 1], p_c,
                                          (const float*)nullptr, x_prev);
        proj_mma<<<dim3(O_DIM / 32, 4), 256>>>(hbuf[(s + 1) & 1]);
        logsoftmax_kernel<<<B_SZ, 256>>>(out + (size_t)d * B_SZ * O_DIM, b_out);
    }

    // final h is in hbuf[(128+31) & 1] == hbuf[1]
    copy_hc_kernel<<<(B_SZ * H_DIM + 255) / 256, 256>>>(
        hbuf[(S_LEN + T_OUT - 1) & 1], out + (size_t)T_OUT * B_SZ * O_DIM);
}

// round 8
// speedup vs baseline: 1.8391x; 1.7886x over previous
#include <cuda_runtime.h>
#include <math.h>
#include <stdint.h>

#define S_LEN 128
#define B_SZ  64
#define I_DIM 1024
#define H_DIM 1024
#define O_DIM 1024
#define G4    4096
#define T_OUT 32
#define NBLK  128
#define ROW64 65536   // 64*1024

// ---------------- scratch (static device globals) ----------------------------
__device__ float g_WihT[I_DIM * G4];        // [k][4H] hi  (big gemm)
__device__ float g_WihT_lo[I_DIM * G4];
__device__ float g_WoutT[H_DIM * O_DIM];    // [k][O] hi
__device__ float g_WoutT_lo[H_DIM * O_DIM];
__device__ float g_WhhPh[NBLK * 1024 * 32]; // packed [blk][k][c], c=gate*8+jj
__device__ float g_WhhPl[NBLK * 1024 * 32];
__device__ float g_WihPh[NBLK * 1024 * 32];
__device__ float g_WihPl[NBLK * 1024 * 32];
__device__ float g_bias[G4];
__device__ float g_XgP[(size_t)NBLK * S_LEN * 2048];  // [blk][t][m*32+c]
__device__ float g_hA[ROW64];
__device__ float g_hB[ROW64];
__device__ float g_c[ROW64];
__device__ float g_pp[4][B_SZ][O_DIM];
__device__ unsigned g_bar_count;
__device__ volatile unsigned g_bar_gen;

// ---------------- tf32 helpers ------------------------------------------------
__device__ __forceinline__ uint32_t f2tf32(float f) {
    uint32_t u;
    asm("cvt.rna.tf32.f32 %0, %1;" : "=r"(u) : "f"(f));
    return u;
}
__device__ __forceinline__ void split_tf32(float v, uint32_t& hi, uint32_t& lo) {
    hi = f2tf32(v);
    lo = f2tf32(v - __uint_as_float(hi));
}
__device__ __forceinline__ void mma8(float c[4],
                                     uint32_t a0, uint32_t a1, uint32_t a2, uint32_t a3,
                                     uint32_t b0, uint32_t b1) {
    asm volatile(
        "mma.sync.aligned.m16n8k8.row.col.f32.tf32.tf32.f32 "
        "{%0,%1,%2,%3}, {%4,%5,%6,%7}, {%8,%9}, {%0,%1,%2,%3};"
        : "+f"(c[0]), "+f"(c[1]), "+f"(c[2]), "+f"(c[3])
        : "r"(a0), "r"(a1), "r"(a2), "r"(a3), "r"(b0), "r"(b1));
}
__device__ __forceinline__ void mma3(float c[4],
                                     const uint32_t ah[4], const uint32_t al[4],
                                     uint32_t bh0, uint32_t bh1,
                                     uint32_t bl0, uint32_t bl1) {
    mma8(c, al[0], al[1], al[2], al[3], bh0, bh1);
    mma8(c, ah[0], ah[1], ah[2], ah[3], bl0, bl1);
    mma8(c, ah[0], ah[1], ah[2], ah[3], bh0, bh1);
}

// ---------------- transpose + tf32 hi/lo split: dst[c][r] = src[r][c] --------
__global__ void transpose_split_kernel(float* __restrict__ dst_hi,
                                       float* __restrict__ dst_lo,
                                       const float* __restrict__ src,
                                       int rows, int cols) {
    __shared__ float tile[32][33];
    int bx = blockIdx.x * 32, by = blockIdx.y * 32;
    int x = bx + threadIdx.x;
    int y = by + threadIdx.y;
#pragma unroll
    for (int i = 0; i < 32; i += 8)
        tile[threadIdx.y + i][threadIdx.x] = src[(size_t)(y + i) * cols + x];
    __syncthreads();
    int xo = by + threadIdx.x;
    int yo = bx + threadIdx.y;
#pragma unroll
    for (int i = 0; i < 32; i += 8) {
        float v = tile[threadIdx.x][threadIdx.y + i];
        uint32_t hi, lo;
        split_tf32(v, hi, lo);
        size_t o = (size_t)(yo + i) * rows + xo;
        dst_hi[o] = __uint_as_float(hi);
        dst_lo[o] = __uint_as_float(lo);
    }
}

// ---------------- pack W[4H][1024] -> P[blk][k][c] (c=gate*8+jj), split ------
__global__ void pack_split_kernel(const float* __restrict__ W,
                                  float* __restrict__ Ph, float* __restrict__ Pl) {
    __shared__ float tile[32][33];
    int blk = blockIdx.y, k0 = blockIdx.x * 32;
    int tx = threadIdx.x, ty = threadIdx.y;   // 32 x 8
#pragma unroll
    for (int i = 0; i < 32; i += 8) {
        int c = ty + i;
        int row = (c >> 3) * 1024 + blk * 8 + (c & 7);
        tile[c][tx] = W[(size_t)row * 1024 + k0 + tx];
    }
    __syncthreads();
#pragma unroll
    for (int i = 0; i < 32; i += 8) {
        int kk = ty + i;
        float v = tile[tx][kk];
        uint32_t hi, lo;
        split_tf32(v, hi, lo);
        size_t o = (size_t)blk * 32768 + (size_t)(k0 + kk) * 32 + tx;
        Ph[o] = __uint_as_float(hi);
        Pl[o] = __uint_as_float(lo);
    }
}

// ---------------- bias fold + state init ------------------------------------
__global__ void prep_state_kernel(const float* __restrict__ h0, const float* __restrict__ c0,
                                  const float* __restrict__ b_ih, const float* __restrict__ b_hh) {
    int i = blockIdx.x * blockDim.x + threadIdx.x;
    if (i < G4) g_bias[i] = b_ih[i] + b_hh[i];
    if (i < ROW64) { g_hA[i] = h0[i]; g_c[i] = c0[i]; }
    if (i == 0) g_bar_count = 0;
}

// ---------------- big input GEMM (3xTF32, pipelined): XgP = input @ WihT ------
// C[8192,4096], tile 128x64, K-chunk 32, 8 warps (4m x 2n), warp m32 x n32.
__global__ __launch_bounds__(256) void gemm_xg_mma(const float* __restrict__ A) {
    __shared__ float    Af[128][36];
    __shared__ uint32_t Bh[32][68], Bl[32][68];
    int tid = threadIdx.x, wid = tid >> 5, lane = tid & 31;
    int row0 = blockIdx.y * 128, col0 = blockIdx.x * 64;
    int wm0 = (wid & 3) * 32, wn0 = (wid >> 2) * 32;
    int gq = lane >> 2, tq = lane & 3;
    float acc[2][4][4] = {};

    int am = tid >> 3, ak4 = (tid & 7) * 4;   // A stage: rows am+32i, cols ak4..+3
    float4 va[4], wh[2], wl[2];
#pragma unroll
    for (int i = 0; i < 4; ++i)
        va[i] = *(const float4*)(A + (size_t)(row0 + am + i * 32) * 1024 + ak4);
#pragma unroll
    for (int i = 0; i < 2; ++i) {
        int idx4 = tid + i * 256;
        int bk = idx4 >> 4, bn4 = (idx4 & 15) * 4;
        size_t o = (size_t)bk * G4 + col0 + bn4;
        wh[i] = *(const float4*)(g_WihT + o);
        wl[i] = *(const float4*)(g_WihT_lo + o);
    }

    for (int k0 = 0; k0 < 1024; k0 += 32) {
#pragma unroll
        for (int i = 0; i < 4; ++i)
            *(float4*)&Af[am + i * 32][ak4] = va[i];
#pragma unroll
        for (int i = 0; i < 2; ++i) {
            int idx4 = tid + i * 256;
            int bk = idx4 >> 4, bn4 = (idx4 & 15) * 4;
            *(float4*)&Bh[bk][bn4] = *(float4*)&wh[i];
            *(float4*)&Bl[bk][bn4] = *(float4*)&wl[i];
        }
        __syncthreads();
        if (k0 + 32 < 1024) {
            int kn = k0 + 32;
#pragma unroll
            for (int i = 0; i < 4; ++i)
                va[i] = *(const float4*)(A + (size_t)(row0 + am + i * 32) * 1024 + kn + ak4);
#pragma unroll
            for (int i = 0; i < 2; ++i) {
                int idx4 = tid + i * 256;
                int bk = idx4 >> 4, bn4 = (idx4 & 15) * 4;
                size_t o = (size_t)(kn + bk) * G4 + col0 + bn4;
                wh[i] = *(const float4*)(g_WihT + o);
                wl[i] = *(const float4*)(g_WihT_lo + o);
            }
        }
#pragma unroll
        for (int k8 = 0; k8 < 4; ++k8) {
            int kk = k8 * 8;
            uint32_t ah[2][4], al[2][4];
#pragma unroll
            for (int ma = 0; ma < 2; ++ma) {
                int r = wm0 + ma * 16 + gq;
                float a0 = Af[r][kk + tq],     a1 = Af[r + 8][kk + tq];
                float a2 = Af[r][kk + tq + 4], a3 = Af[r + 8][kk + tq + 4];
                split_tf32(a0, ah[ma][0], al[ma][0]);
                split_tf32(a1, ah[ma][1], al[ma][1]);
                split_tf32(a2, ah[ma][2], al[ma][2]);
                split_tf32(a3, ah[ma][3], al[ma][3]);
            }
#pragma unroll
            for (int na = 0; na < 4; ++na) {
                int nc = wn0 + na * 8 + gq;
                uint32_t bh0 = Bh[kk + tq][nc], bh1 = Bh[kk + tq + 4][nc];
                uint32_t bl0 = Bl[kk + tq][nc], bl1 = Bl[kk + tq + 4][nc];
#pragma unroll
                for (int ma = 0; ma < 2; ++ma)
                    mma3(acc[ma][na], ah[ma], al[ma], bh0, bh1, bl0, bl1);
            }
        }
        __syncthreads();
    }
    // epilogue -> packed XgP[blk][t][m*32 + gate*8+jj]
#pragma unroll
    for (int ma = 0; ma < 2; ++ma)
#pragma unroll
        for (int na = 0; na < 4; ++na) {
            int r = row0 + wm0 + ma * 16 + gq;
            int cc = col0 + wn0 + na * 8 + 2 * tq;
            int t = r >> 6, m = r & 63;
            int blk = (cc & 1023) >> 3;
            int cpk = (cc >> 10) * 8 + (cc & 7);
            float* dst = g_XgP + ((size_t)blk * S_LEN + t) * 2048 + m * 32 + cpk;
            *(float2*)dst = make_float2(acc[ma][na][0], acc[ma][na][1]);
            *(float2*)(g_XgP + ((size_t)blk * S_LEN + t) * 2048 + (m + 8) * 32 + cpk) =
                make_float2(acc[ma][na][2], acc[ma][na][3]);
        }
}

// ---------------- grid-wide barrier ------------------------------------------
__device__ __forceinline__ void grid_sync() {
    __syncthreads();
    if (threadIdx.x == 0) {
        unsigned gen = g_bar_gen;
        __threadfence();
        if (atomicAdd(&g_bar_count, 1u) == NBLK - 1u) {
            atomicExch(&g_bar_count, 0u);
            __threadfence();
            g_bar_gen = gen + 1;
        } else {
            while (g_bar_gen == gen) __nanosleep(64);
            __threadfence();
        }
    }
    __syncthreads();
}

// ---------------- one 3xTF32 GEMM pass for the cell (pipelined) --------------
// acc += V[64x1024] @ Wpacked[1024x32]. V read with .cg (cross-SM data).
__device__ __forceinline__ void gemm_pass_cell(
    const float* __restrict__ V, const float* __restrict__ Ph, const float* __restrict__ Pl,
    float (*Af)[36], uint32_t (*Bh)[36], uint32_t (*Bl)[36],
    float acc[2][4], int tid, int m0, int nb, int gq, int tq)
{
    int am = tid >> 3, ak4 = (tid & 7) * 4;
    float4 v0 = __ldcg((const float4*)(V + (size_t)am * 1024 + ak4));
    float4 v1 = __ldcg((const float4*)(V + (size_t)(am + 32) * 1024 + ak4));
    float4 wh = __ldg((const float4*)(Ph + tid * 4));
    float4 wl = __ldg((const float4*)(Pl + tid * 4));
    for (int ch = 0; ch < 32; ++ch) {
        *(float4*)&Af[am][ak4] = v0;
        *(float4*)&Af[am + 32][ak4] = v1;
        *(float4*)&Bh[tid >> 3][(tid & 7) * 4] = *(float4*)&wh;
        *(float4*)&Bl[tid >> 3][(tid & 7) * 4] = *(float4*)&wl;
        __syncthreads();
        if (ch < 31) {
            int kn = (ch + 1) * 32;
            v0 = __ldcg((const float4*)(V + (size_t)am * 1024 + kn + ak4));
            v1 = __ldcg((const float4*)(V + (size_t)(am + 32) * 1024 + kn + ak4));
            wh = __ldg((const float4*)(Ph + (ch + 1) * 1024 + tid * 4));
            wl = __ldg((const float4*)(Pl + (ch + 1) * 1024 + tid * 4));
        }
#pragma unroll
        for (int k8 = 0; k8 < 4; ++k8) {
            int kk = k8 * 8;
            float a0 = Af[m0 + gq][kk + tq],     a1 = Af[m0 + gq + 8][kk + tq];
            float a2 = Af[m0 + gq][kk + tq + 4], a3 = Af[m0 + gq + 8][kk + tq + 4];
            uint32_t ah[4], al[4];
            split_tf32(a0, ah[0], al[0]);
            split_tf32(a1, ah[1], al[1]);
            split_tf32(a2, ah[2], al[2]);
            split_tf32(a3, ah[3], al[3]);
#pragma unroll
            for (int na = 0; na < 2; ++na) {
                int nc = (nb + na) * 8 + gq;
                mma3(acc[na], ah, al, Bh[kk + tq][nc], Bh[kk + tq + 4][nc],
                     Bl[kk + tq][nc], Bl[kk + tq + 4][nc]);
            }
        }
        __syncthreads();
    }
}

// ---------------- persistent kernel: encode + decode -------------------------
__global__ __launch_bounds__(256, 1) void lstm_persistent(float* __restrict__ out,
                                                          const float* __restrict__ b_out) {
    __shared__ float    Af[64][36];
    __shared__ uint32_t Bh[32][36], Bl[32][36];
    __shared__ float    Gs[64][33];
    __shared__ float    red[8];
    __shared__ float    s_lse;

    int bid = blockIdx.x, tid = threadIdx.x;
    int wid = tid >> 5, lane = tid & 31;
    int m0 = (wid & 3) * 16, nb = (wid >> 2) * 2;
    int gq = lane >> 2, tq = lane & 3;
    int j0 = bid * 8;

    const float* WhhH = g_WhhPh + (size_t)bid * 32768;
    const float* WhhL = g_WhhPl + (size_t)bid * 32768;
    const float* WihH = g_WihPh + (size_t)bid * 32768;
    const float* WihL = g_WihPl + (size_t)bid * 32768;
    float* hb[2] = {g_hA, g_hB};

    // ---- cell epilogue lambda-ish (macroless, inline twice) ----
    auto cell_epilogue = [&](float acc[2][4], float* h_out, const float* xg) {
#pragma unroll
        for (int na = 0; na < 2; ++na) {
            int col = (nb + na) * 8 + 2 * tq;
            Gs[m0 + gq][col]         = acc[na][0];
            Gs[m0 + gq][col + 1]     = acc[na][1];
            Gs[m0 + gq + 8][col]     = acc[na][2];
            Gs[m0 + gq + 8][col + 1] = acc[na][3];
        }
        __syncthreads();
#pragma unroll
        for (int p = 0; p < 2; ++p) {
            int idx = tid + p * 256;
            int m = idx >> 3, jj = idx & 7;
            float gi = Gs[m][jj]      + __ldg(&g_bias[j0 + jj]);
            float gf = Gs[m][8 + jj]  + __ldg(&g_bias[1024 + j0 + jj]);
            float gg = Gs[m][16 + jj] + __ldg(&g_bias[2048 + j0 + jj]);
            float go = Gs[m][24 + jj] + __ldg(&g_bias[3072 + j0 + jj]);
            if (xg) {
                const float* x = xg + m * 32;
                gi += x[jj]; gf += x[8 + jj]; gg += x[16 + jj]; go += x[24 + jj];
            }
            int off = m * 1024 + j0 + jj;
            float cold = g_c[off];
            float si = 1.f / (1.f + expf(-gi));
            float sf = 1.f / (1.f + expf(-gf));
            float so = 1.f / (1.f + expf(-go));
            float cn = sf * cold + si * tanhf(gg);
            g_c[off] = cn;
            __stcg(h_out + off, so * tanhf(cn));
        }
    };

    auto proj_pass = [&](const float* h) {
        int col0 = (bid & 31) * 32;
        int ks = bid >> 5;
        int kbase = ks * 256;
        float acc[2][4] = {};
        int am = tid >> 3, ak4 = (tid & 7) * 4;
        for (int ch = 0; ch < 8; ++ch) {
            int k0 = kbase + ch * 32;
            float4 v0 = __ldcg((const float4*)(h + (size_t)am * 1024 + k0 + ak4));
            float4 v1 = __ldcg((const float4*)(h + (size_t)(am + 32) * 1024 + k0 + ak4));
            *(float4*)&Af[am][ak4] = v0;
            *(float4*)&Af[am + 32][ak4] = v1;
            {
                int bk = tid >> 3, bn4 = (tid & 7) * 4;
                size_t o = (size_t)(k0 + bk) * 1024 + col0 + bn4;
                *(float4*)&Bh[bk][bn4] = *(const float4*)(g_WoutT + o);
                *(float4*)&Bl[bk][bn4] = *(const float4*)(g_WoutT_lo + o);
            }
            __syncthreads();
#pragma unroll
            for (int k8 = 0; k8 < 4; ++k8) {
                int kk = k8 * 8;
                float a0 = Af[m0 + gq][kk + tq],     a1 = Af[m0 + gq + 8][kk + tq];
                float a2 = Af[m0 + gq][kk + tq + 4], a3 = Af[m0 + gq + 8][kk + tq + 4];
                uint32_t ah[4], al[4];
                split_tf32(a0, ah[0], al[0]);
                split_tf32(a1, ah[1], al[1]);
                split_tf32(a2, ah[2], al[2]);
                split_tf32(a3, ah[3], al[3]);
#pragma unroll
                for (int na = 0; na < 2; ++na) {
                    int nc = (nb + na) * 8 + gq;
                    mma3(acc[na], ah, al, Bh[kk + tq][nc], Bh[kk + tq + 4][nc],
                         Bl[kk + tq][nc], Bl[kk + tq + 4][nc]);
                }
            }
            __syncthreads();
        }
#pragma unroll
        for (int na = 0; na < 2; ++na) {
            int cc = col0 + (nb + na) * 8 + 2 * tq;
            int r = m0 + gq;
            __stcg((float2*)&g_pp[ks][r][cc],     make_float2(acc[na][0], acc[na][1]));
            __stcg((float2*)&g_pp[ks][r + 8][cc], make_float2(acc[na][2], acc[na][3]));
        }
    };

    auto softmax_row = [&](float* dst) {
        // blocks 0..63 each handle one batch row
        int b = bid;
        float* row = &Gs[0][0];   // 2112 floats >= 1024
        float lm = -1e30f;
        for (int o = tid; o < 1024; o += 256) {
            float v = __ldcg(&g_pp[0][b][o]) + __ldcg(&g_pp[1][b][o])
                    + __ldcg(&g_pp[2][b][o]) + __ldcg(&g_pp[3][b][o])
                    + __ldg(&b_out[o]);
            row[o] = v;
            lm = fmaxf(lm, v);
        }
#pragma unroll
        for (int s = 16; s; s >>= 1) lm = fmaxf(lm, __shfl_xor_sync(0xffffffffu, lm, s));
        if (lane == 0) red[wid] = lm;
        __syncthreads();
        if (tid == 0) {
            float mm = red[0];
#pragma unroll
            for (int i = 1; i < 8; ++i) mm = fmaxf(mm, red[i]);
            red[0] = mm;
        }
        __syncthreads();
        float mm = red[0];
        float s = 0.f;
        for (int o = tid; o < 1024; o += 256) s += expf(row[o] - mm);
#pragma unroll
        for (int sh = 16; sh; sh >>= 1) s += __shfl_xor_sync(0xffffffffu, s, sh);
        if (lane == 0) red[wid] = s;
        __syncthreads();
        if (tid == 0) {
            float tot = 0.f;
#pragma unroll
            for (int i = 0; i < 8; ++i) tot += red[i];
            s_lse = mm + logf(tot);
        }
        __syncthreads();
        float lse = s_lse;
        for (int o = tid; o < 1024; o += 256) __stcg(&dst[o], row[o] - lse);
        __syncthreads();
    };

    // ================= encode: 128 steps =================
    for (int t = 0; t < S_LEN; ++t) {
        float acc[2][4] = {};
        gemm_pass_cell(hb[t & 1], WhhH, WhhL, Af, Bh, Bl, acc, tid, m0, nb, gq, tq);
        cell_epilogue(acc, hb[(t + 1) & 1],
                      g_XgP + ((size_t)bid * S_LEN + t) * 2048);
        grid_sync();
    }

    // ================= first projection + softmax =================
    proj_pass(hb[0]);
    grid_sync();
    if (bid < 64) softmax_row(out + (size_t)bid * 1024);
    grid_sync();

    // ================= autoregressive decode =================
    for (int d = 1; d < T_OUT; ++d) {
        int s = S_LEN + d - 1;
        const float* x = out + (size_t)(d - 1) * ROW64;
        float acc[2][4] = {};
        gemm_pass_cell(hb[s & 1], WhhH, WhhL, Af, Bh, Bl, acc, tid, m0, nb, gq, tq);
        gemm_pass_cell(x, WihH, WihL, Af, Bh, Bl, acc, tid, m0, nb, gq, tq);
        cell_epilogue(acc, hb[(s + 1) & 1], nullptr);
        grid_sync();
        proj_pass(hb[(s + 1) & 1]);
        grid_sync();
        if (bid < 64) softmax_row(out + (size_t)d * ROW64 + (size_t)bid * 1024);
        grid_sync();
    }

    // ================= final h, c =================
    float* oc = out + (size_t)T_OUT * ROW64;
#pragma unroll
    for (int p = 0; p < 2; ++p) {
        int idx = tid + p * 256;
        int m = idx >> 3, jj = idx & 7;
        int off = m * 1024 + j0 + jj;
        oc[off] = __ldcg(hb[1] + off);
        oc[ROW64 + off] = g_c[off];
    }
}

// ---------------- host orchestration -----------------------------------------
extern "C" void kernel_launch(void* const* d_in, const int* in_sizes, int n_in,
                              void* d_out, int out_size) {
    const float* input = (const float*)d_in[0];
    const float* h0    = (const float*)d_in[1];
    const float* c0    = (const float*)d_in[2];
    const float* W_ih  = (const float*)d_in[3];
    const float* W_hh  = (const float*)d_in[4];
    const float* b_ih  = (const float*)d_in[5];
    const float* b_hh  = (const float*)d_in[6];
    const float* W_out = (const float*)d_in[7];
    const float* b_out = (const float*)d_in[8];
    float* out = (float*)d_out;

    float *p_WihT, *p_WihT_lo, *p_WoutT, *p_WoutT_lo;
    float *p_WhhPh, *p_WhhPl, *p_WihPh, *p_WihPl;
    cudaGetSymbolAddress((void**)&p_WihT, g_WihT);
    cudaGetSymbolAddress((void**)&p_WihT_lo, g_WihT_lo);
    cudaGetSymbolAddress((void**)&p_WoutT, g_WoutT);
    cudaGetSymbolAddress((void**)&p_WoutT_lo, g_WoutT_lo);
    cudaGetSymbolAddress((void**)&p_WhhPh, g_WhhPh);
    cudaGetSymbolAddress((void**)&p_WhhPl, g_WhhPl);
    cudaGetSymbolAddress((void**)&p_WihPh, g_WihPh);
    cudaGetSymbolAddress((void**)&p_WihPl, g_WihPl);

    dim3 tb(32, 8);
    // WihT [k][4H] hi/lo for the big input GEMM
    transpose_split_kernel<<<dim3(I_DIM / 32, G4 / 32), tb>>>(p_WihT, p_WihT_lo, W_ih, G4, I_DIM);
    // WoutT [k][O] hi/lo for projection
    transpose_split_kernel<<<dim3(H_DIM / 32, O_DIM / 32), tb>>>(p_WoutT, p_WoutT_lo, W_out, O_DIM, H_DIM);
    // packed per-block weight slices for the recurrent + decode-x GEMMs
    pack_split_kernel<<<dim3(32, NBLK), tb>>>(W_hh, p_WhhPh, p_WhhPl);
    pack_split_kernel<<<dim3(32, NBLK), tb>>>(W_ih, p_WihPh, p_WihPl);
    prep_state_kernel<<<(ROW64 + 255) / 256, 256>>>(h0, c0, b_ih, b_hh);

    // XgP = input @ WihT, written pre-packed per (block, t)
    gemm_xg_mma<<<dim3(G4 / 64, (S_LEN * B_SZ) / 128), 256>>>(input);

    // the whole recurrence + decode in ONE persistent kernel
    lstm_persistent<<<NBLK, 256>>>(out, b_out);
}

// round 9
// speedup vs baseline: 2.4199x; 1.3158x over previous
#include <cuda_runtime.h>
#include <cuda_bf16.h>
#include <math.h>
#include <stdint.h>

#define S_LEN 128
#define B_SZ  64
#define G4    4096
#define T_OUT 32
#define NBLK  128
#define ROW64 65536   // 64*1024

// ---------------- device globals ---------------------------------------------
__device__ uint32_t g_BbigH[512 * 4096];      // big-gemm B  [k2][n] bf16x2 hi
__device__ uint32_t g_BbigL[512 * 4096];      //                         lo
__device__ uint32_t g_PhhH[NBLK * 16384];     // Whh slice [blk][k2][32]
__device__ uint32_t g_PhhL[NBLK * 16384];
__device__ uint32_t g_PihH[NBLK * 16384];     // Wih slice (decode x-gemm)
__device__ uint32_t g_PihL[NBLK * 16384];
__device__ uint32_t g_PoutH[NBLK * 4096];     // Wout slice [blk][k2l][32]
__device__ uint32_t g_PoutL[NBLK * 4096];
__device__ float g_bias[G4];
__device__ float g_XgP[(size_t)NBLK * S_LEN * 2048];  // packed input gates
__device__ float g_hA[ROW64];
__device__ float g_hB[ROW64];
__device__ float g_c[ROW64];
__device__ float g_pp[4][B_SZ][1024];
__device__ unsigned g_bar_count;
__device__ volatile unsigned g_bar_gen;

// ---------------- smem layout of the persistent kernel (u32 units) -----------
#define W_STRIDE 520
#define OFF_WTH 0
#define OFF_WTL 16640
#define OFF_AH  33280   // [64][36]
#define OFF_AL  35584
#define OFF_BSH 37888   // [32][40]
#define OFF_BSL 39168
#define OFF_GS  40448   // float[64][33]
#define OFF_RED 42560
#define OFF_LSE 42568
#define SMEM_U32 42576
#define SMEM_BYTES (SMEM_U32 * 4)

// ---------------- bf16x2 helpers ----------------------------------------------
__device__ __forceinline__ void split_pair(float v0, float v1, uint32_t& h2, uint32_t& l2) {
    __nv_bfloat162 h = __floats2bfloat162_rn(v0, v1);      // .x = v0 (lower)
    float r0 = __bfloat162float(__low2bfloat16(h));
    float r1 = __bfloat162float(__high2bfloat16(h));
    __nv_bfloat162 l = __floats2bfloat162_rn(v0 - r0, v1 - r1);
    h2 = *reinterpret_cast<uint32_t*>(&h);
    l2 = *reinterpret_cast<uint32_t*>(&l);
}
__device__ __forceinline__ void mmab(float c[4],
                                     uint32_t a0, uint32_t a1, uint32_t a2, uint32_t a3,
                                     uint32_t b0, uint32_t b1) {
    asm volatile(
        "mma.sync.aligned.m16n8k16.row.col.f32.bf16.bf16.f32 "
        "{%0,%1,%2,%3}, {%4,%5,%6,%7}, {%8,%9}, {%0,%1,%2,%3};"
        : "+f"(c[0]), "+f"(c[1]), "+f"(c[2]), "+f"(c[3])
        : "r"(a0), "r"(a1), "r"(a2), "r"(a3), "r"(b0), "r"(b1));
}
__device__ __forceinline__ void mma3b(float c[4],
                                      const uint32_t ah[4], const uint32_t al[4],
                                      uint32_t bh0, uint32_t bh1,
                                      uint32_t bl0, uint32_t bl1) {
    mmab(c, al[0], al[1], al[2], al[3], bh0, bh1);
    mmab(c, ah[0], ah[1], ah[2], ah[3], bl0, bl1);
    mmab(c, ah[0], ah[1], ah[2], ah[3], bh0, bh1);
}

// ---------------- pack kernels ------------------------------------------------
// cell weights: W[4096][1024] -> P[blk][k2][32] (c = gate*8 + jj)
__global__ void pack_cell_w(const float* __restrict__ W,
                            uint32_t* __restrict__ Ph, uint32_t* __restrict__ Pl) {
    __shared__ float tile[32][33];
    int blk = blockIdx.y, k0 = blockIdx.x * 32;
    int tx = threadIdx.x, ty = threadIdx.y;   // 32 x 8
#pragma unroll
    for (int i = 0; i < 32; i += 8) {
        int c = ty + i;
        int row = (c >> 3) * 1024 + blk * 8 + (c & 7);
        tile[c][tx] = W[(size_t)row * 1024 + k0 + tx];
    }
    __syncthreads();
#pragma unroll
    for (int i = 0; i < 16; i += 8) {
        int k2l = ty + i;
        uint32_t h2, l2;
        split_pair(tile[tx][2 * k2l], tile[tx][2 * k2l + 1], h2, l2);
        size_t o = (size_t)blk * 16384 + (size_t)((k0 >> 1) + k2l) * 32 + tx;
        Ph[o] = h2; Pl[o] = l2;
    }
}

// big-gemm B: W_ih[4096][1024] -> Bbig[k2][n]
__global__ void pack_big_w(const float* __restrict__ W) {
    __shared__ float tile[32][33];
    int n0 = blockIdx.y * 32, k0 = blockIdx.x * 32;
    int tx = threadIdx.x, ty = threadIdx.y;
#pragma unroll
    for (int i = 0; i < 32; i += 8)
        tile[ty + i][tx] = W[(size_t)(n0 + ty + i) * 1024 + k0 + tx];   // [n][k]
    __syncthreads();
#pragma unroll
    for (int i = 0; i < 16; i += 8) {
        int k2l = ty + i;
        uint32_t h2, l2;
        split_pair(tile[tx][2 * k2l], tile[tx][2 * k2l + 1], h2, l2);
        size_t o = (size_t)((k0 >> 1) + k2l) * 4096 + n0 + tx;
        g_BbigH[o] = h2; g_BbigL[o] = l2;
    }
}

// proj weights: W_out[1024][1024] -> Pout[bid][k2l][32]
__global__ void pack_out_w(const float* __restrict__ W) {
    __shared__ float tile[32][33];
    int bid = blockIdx.y;
    int col0 = (bid & 31) * 32, kbase = (bid >> 5) * 256;
    int k0 = kbase + blockIdx.x * 32;
    int tx = threadIdx.x, ty = threadIdx.y;
#pragma unroll
    for (int i = 0; i < 32; i += 8) {
        int c = ty + i;
        tile[c][tx] = W[(size_t)(col0 + c) * 1024 + k0 + tx];
    }
    __syncthreads();
#pragma unroll
    for (int i = 0; i < 16; i += 8) {
        int k2l = ty + i;
        uint32_t h2, l2;
        split_pair(tile[tx][2 * k2l], tile[tx][2 * k2l + 1], h2, l2);
        size_t o = (size_t)bid * 4096 + (size_t)(blockIdx.x * 16 + k2l) * 32 + tx;
        g_PoutH[o] = h2; g_PoutL[o] = l2;
    }
}

// ---------------- bias fold + state init -------------------------------------
__global__ void prep_state_kernel(const float* __restrict__ h0, const float* __restrict__ c0,
                                  const float* __restrict__ b_ih, const float* __restrict__ b_hh) {
    int i = blockIdx.x * blockDim.x + threadIdx.x;
    if (i < G4) g_bias[i] = b_ih[i] + b_hh[i];
    if (i < ROW64) { g_hA[i] = h0[i]; g_c[i] = c0[i]; }
    if (i == 0) g_bar_count = 0;
}

// ---------------- big input GEMM (bf16x2): XgP = input @ WihT -----------------
// C[8192,4096], tile 128x64, K-chunk 32, 8 warps (4m x 2n), warp m32 x n32.
__global__ __launch_bounds__(256) void gemm_xg_bf16(const float* __restrict__ A) {
    __shared__ uint32_t Ah[128][36], Al[128][36];
    __shared__ uint32_t Bh[16][72], Bl[16][72];
    int tid = threadIdx.x, wid = tid >> 5, lane = tid & 31;
    int row0 = blockIdx.y * 128, col0 = blockIdx.x * 64;
    int wm0 = (wid & 3) * 32, wn0 = (wid >> 2) * 32;
    int gq = lane >> 2, tq = lane & 3;
    float acc[2][4][4] = {};
    for (int k0 = 0; k0 < 1024; k0 += 32) {
#pragma unroll
        for (int i = 0; i < 4; ++i) {
            int idx = tid + i * 256;
            int m = idx >> 3, kq = (idx & 7) * 4;
            float4 v = *(const float4*)(A + (size_t)(row0 + m) * 1024 + k0 + kq);
            uint32_t h0, l0, h1, l1;
            split_pair(v.x, v.y, h0, l0);
            split_pair(v.z, v.w, h1, l1);
            int k2 = kq >> 1;
            *(uint2*)&Ah[m][k2] = make_uint2(h0, h1);
            *(uint2*)&Al[m][k2] = make_uint2(l0, l1);
        }
        {
            int k2 = tid >> 4, n4 = (tid & 15) * 4;
            size_t o = (size_t)((k0 >> 1) + k2) * 4096 + col0 + n4;
            *(uint4*)&Bh[k2][n4] = *(const uint4*)(g_BbigH + o);
            *(uint4*)&Bl[k2][n4] = *(const uint4*)(g_BbigL + o);
        }
        __syncthreads();
#pragma unroll
        for (int kk2 = 0; kk2 < 16; kk2 += 8) {
            uint32_t ah[2][4], al[2][4];
#pragma unroll
            for (int ma = 0; ma < 2; ++ma) {
                int r = wm0 + ma * 16 + gq;
                ah[ma][0] = Ah[r][kk2 + tq];     ah[ma][1] = Ah[r + 8][kk2 + tq];
                ah[ma][2] = Ah[r][kk2 + tq + 4]; ah[ma][3] = Ah[r + 8][kk2 + tq + 4];
                al[ma][0] = Al[r][kk2 + tq];     al[ma][1] = Al[r + 8][kk2 + tq];
                al[ma][2] = Al[r][kk2 + tq + 4]; al[ma][3] = Al[r + 8][kk2 + tq + 4];
            }
#pragma unroll
            for (int na = 0; na < 4; ++na) {
                int nc = wn0 + na * 8 + gq;
                uint32_t bh0 = Bh[kk2 + tq][nc], bh1 = Bh[kk2 + tq + 4][nc];
                uint32_t bl0 = Bl[kk2 + tq][nc], bl1 = Bl[kk2 + tq + 4][nc];
#pragma unroll
                for (int ma = 0; ma < 2; ++ma)
                    mma3b(acc[ma][na], ah[ma], al[ma], bh0, bh1, bl0, bl1);
            }
        }
        __syncthreads();
    }
    // epilogue -> packed XgP[blk][t][m*32 + gate*8+jj]
#pragma unroll
    for (int ma = 0; ma < 2; ++ma)
#pragma unroll
        for (int na = 0; na < 4; ++na) {
            int r = row0 + wm0 + ma * 16 + gq;
            int cc = col0 + wn0 + na * 8 + 2 * tq;
            int t = r >> 6, m = r & 63;
            int blk = (cc & 1023) >> 3;
            int cpk = (cc >> 10) * 8 + (cc & 7);
            *(float2*)(g_XgP + ((size_t)blk * S_LEN + t) * 2048 + m * 32 + cpk) =
                make_float2(acc[ma][na][0], acc[ma][na][1]);
            *(float2*)(g_XgP + ((size_t)blk * S_LEN + t) * 2048 + (m + 8) * 32 + cpk) =
                make_float2(acc[ma][na][2], acc[ma][na][3]);
        }
}

// ---------------- grid-wide barrier ------------------------------------------
__device__ __forceinline__ void grid_sync() {
    __syncthreads();
    if (threadIdx.x == 0) {
        unsigned gen = g_bar_gen;
        __threadfence();
        if (atomicAdd(&g_bar_count, 1u) == NBLK - 1u) {
            atomicExch(&g_bar_count, 0u);
            __threadfence();
            g_bar_gen = gen + 1;
        } else {
            while (g_bar_gen == gen) __nanosleep(64);
            __threadfence();
        }
    }
    __syncthreads();
}

// ---------------- persistent kernel: encode + decode -------------------------
__global__ __launch_bounds__(256, 1) void lstm_persistent(float* __restrict__ out,
                                                          const float* __restrict__ b_out) {
    extern __shared__ uint32_t sm[];
    uint32_t* Wth = sm + OFF_WTH;
    uint32_t* Wtl = sm + OFF_WTL;
    uint32_t* Ah  = sm + OFF_AH;    // [64][36]
    uint32_t* Al  = sm + OFF_AL;
    uint32_t* Bsh = sm + OFF_BSH;   // [32][40]
    uint32_t* Bsl = sm + OFF_BSL;
    float* Gs  = (float*)(sm + OFF_GS);   // [64][33]
    float* red = (float*)(sm + OFF_RED);
    float* plse = (float*)(sm + OFF_LSE);

    int bid = blockIdx.x, tid = threadIdx.x;
    int wid = tid >> 5, lane = tid & 31;
    int m0 = (wid & 3) * 16, nb = (wid >> 2) * 2;
    int gq = lane >> 2, tq = lane & 3;
    int j0 = bid * 8;

    // ---- load this block's Whh slice into smem, transposed [c][k2] ----
    {
        const uint32_t* Ph = g_PhhH + (size_t)bid * 16384;
        const uint32_t* Pl = g_PhhL + (size_t)bid * 16384;
#pragma unroll 4
        for (int i = 0; i < 64; ++i) {
            int idx = tid + i * 256;
            int k2 = idx >> 5, c = idx & 31;
            Wth[c * W_STRIDE + k2] = Ph[idx];
            Wtl[c * W_STRIDE + k2] = Pl[idx];
        }
    }
    __syncthreads();

    float* hb[2] = {g_hA, g_hB};

    // ---- cell gemm with smem-resident weights: acc += V @ Whh_slice ----
    auto cell_pass_smemW = [&](const float* V, float acc[2][4]) {
        for (int ch = 0; ch < 16; ++ch) {
#pragma unroll
            for (int i = 0; i < 4; ++i) {
                int idx = tid + i * 256;
                int m = idx >> 4, kq = (idx & 15) * 4;
                float4 v = __ldcg((const float4*)(V + (size_t)m * 1024 + ch * 64 + kq));
                uint32_t h0, l0, h1, l1;
                split_pair(v.x, v.y, h0, l0);
                split_pair(v.z, v.w, h1, l1);
                int k2 = kq >> 1;
                *(uint2*)&Ah[m * 36 + k2] = make_uint2(h0, h1);
                *(uint2*)&Al[m * 36 + k2] = make_uint2(l0, l1);
            }
            __syncthreads();
#pragma unroll
            for (int kk2 = 0; kk2 < 32; kk2 += 8) {
                int k2g = ch * 32 + kk2;
                uint32_t ah[4], al[4];
                ah[0] = Ah[(m0 + gq) * 36 + kk2 + tq];
                ah[1] = Ah[(m0 + gq + 8) * 36 + kk2 + tq];
                ah[2] = Ah[(m0 + gq) * 36 + kk2 + tq + 4];
                ah[3] = Ah[(m0 + gq + 8) * 36 + kk2 + tq + 4];
                al[0] = Al[(m0 + gq) * 36 + kk2 + tq];
                al[1] = Al[(m0 + gq + 8) * 36 + kk2 + tq];
                al[2] = Al[(m0 + gq) * 36 + kk2 + tq + 4];
                al[3] = Al[(m0 + gq + 8) * 36 + kk2 + tq + 4];
#pragma unroll
                for (int na = 0; na < 2; ++na) {
                    int nc = (nb + na) * 8 + gq;
                    uint32_t bh0 = Wth[nc * W_STRIDE + k2g + tq];
                    uint32_t bh1 = Wth[nc * W_STRIDE + k2g + tq + 4];
                    uint32_t bl0 = Wtl[nc * W_STRIDE + k2g + tq];
                    uint32_t bl1 = Wtl[nc * W_STRIDE + k2g + tq + 4];
                    mma3b(acc[na], ah, al, bh0, bh1, bl0, bl1);
                }
            }
            __syncthreads();
        }
    };

    // ---- cell gemm with streamed weights (decode x-side) ----
    auto cell_pass_streamW = [&](const float* V, const uint32_t* Ph, const uint32_t* Pl,
                                 float acc[2][4]) {
        for (int ch = 0; ch < 16; ++ch) {
#pragma unroll
            for (int i = 0; i < 4; ++i) {
                int idx = tid + i * 256;
                int m = idx >> 4, kq = (idx & 15) * 4;
                float4 v = __ldcg((const float4*)(V + (size_t)m * 1024 + ch * 64 + kq));
                uint32_t h0, l0, h1, l1;
                split_pair(v.x, v.y, h0, l0);
                split_pair(v.z, v.w, h1, l1);
                int k2 = kq >> 1;
                *(uint2*)&Ah[m * 36 + k2] = make_uint2(h0, h1);
                *(uint2*)&Al[m * 36 + k2] = make_uint2(l0, l1);
            }
            {
                int k2l = tid >> 3, c4 = (tid & 7) * 4;
                *(uint4*)&Bsh[k2l * 40 + c4] = *(const uint4*)(Ph + (ch * 32 + k2l) * 32 + c4);
                *(uint4*)&Bsl[k2l * 40 + c4] = *(const uint4*)(Pl + (ch * 32 + k2l) * 32 + c4);
            }
            __syncthreads();
#pragma unroll
            for (int kk2 = 0; kk2 < 32; kk2 += 8) {
                uint32_t ah[4], al[4];
                ah[0] = Ah[(m0 + gq) * 36 + kk2 + tq];
                ah[1] = Ah[(m0 + gq + 8) * 36 + kk2 + tq];
                ah[2] = Ah[(m0 + gq) * 36 + kk2 + tq + 4];
                ah[3] = Ah[(m0 + gq + 8) * 36 + kk2 + tq + 4];
                al[0] = Al[(m0 + gq) * 36 + kk2 + tq];
                al[1] = Al[(m0 + gq + 8) * 36 + kk2 + tq];
                al[2] = Al[(m0 + gq) * 36 + kk2 + tq + 4];
                al[3] = Al[(m0 + gq + 8) * 36 + kk2 + tq + 4];
#pragma unroll
                for (int na = 0; na < 2; ++na) {
                    int nc = (nb + na) * 8 + gq;
                    uint32_t bh0 = Bsh[(kk2 + tq) * 40 + nc];
                    uint32_t bh1 = Bsh[(kk2 + tq + 4) * 40 + nc];
                    uint32_t bl0 = Bsl[(kk2 + tq) * 40 + nc];
                    uint32_t bl1 = Bsl[(kk2 + tq + 4) * 40 + nc];
                    mma3b(acc[na], ah, al, bh0, bh1, bl0, bl1);
                }
            }
            __syncthreads();
        }
    };

    auto cell_epilogue = [&](float acc[2][4], float* h_out, const float* xg) {
#pragma unroll
        for (int na = 0; na < 2; ++na) {
            int col = (nb + na) * 8 + 2 * tq;
            Gs[(m0 + gq) * 33 + col]         = acc[na][0];
            Gs[(m0 + gq) * 33 + col + 1]     = acc[na][1];
            Gs[(m0 + gq + 8) * 33 + col]     = acc[na][2];
            Gs[(m0 + gq + 8) * 33 + col + 1] = acc[na][3];
        }
        __syncthreads();
#pragma unroll
        for (int p = 0; p < 2; ++p) {
            int idx = tid + p * 256;
            int m = idx >> 3, jj = idx & 7;
            float gi = Gs[m * 33 + jj]      + __ldg(&g_bias[j0 + jj]);
            float gf = Gs[m * 33 + 8 + jj]  + __ldg(&g_bias[1024 + j0 + jj]);
            float gg = Gs[m * 33 + 16 + jj] + __ldg(&g_bias[2048 + j0 + jj]);
            float go = Gs[m * 33 + 24 + jj] + __ldg(&g_bias[3072 + j0 + jj]);
            if (xg) {
                const float* x = xg + m * 32;
                gi += x[jj]; gf += x[8 + jj]; gg += x[16 + jj]; go += x[24 + jj];
            }
            int off = m * 1024 + j0 + jj;
            float cold = g_c[off];
            float si = 1.f / (1.f + expf(-gi));
            float sf = 1.f / (1.f + expf(-gf));
            float so = 1.f / (1.f + expf(-go));
            float cn = sf * cold + si * tanhf(gg);
            g_c[off] = cn;
            __stcg(h_out + off, so * tanhf(cn));
        }
        __syncthreads();
    };

    auto proj_pass = [&](const float* h) {
        int col0 = (bid & 31) * 32;
        int ks = bid >> 5;
        int kbase = ks * 256;
        const uint32_t* Ph = g_PoutH + (size_t)bid * 4096;
        const uint32_t* Pl = g_PoutL + (size_t)bid * 4096;
        float acc[2][4] = {};
        for (int ch = 0; ch < 4; ++ch) {
#pragma unroll
            for (int i = 0; i < 4; ++i) {
                int idx = tid + i * 256;
                int m = idx >> 4, kq = (idx & 15) * 4;
                float4 v = __ldcg((const float4*)(h + (size_t)m * 1024 + kbase + ch * 64 + kq));
                uint32_t h0, l0, h1, l1;
                split_pair(v.x, v.y, h0, l0);
                split_pair(v.z, v.w, h1, l1);
                int k2 = kq >> 1;
                *(uint2*)&Ah[m * 36 + k2] = make_uint2(h0, h1);
                *(uint2*)&Al[m * 36 + k2] = make_uint2(l0, l1);
            }
            {
                int k2l = tid >> 3, c4 = (tid & 7) * 4;
                *(uint4*)&Bsh[k2l * 40 + c4] = *(const uint4*)(Ph + (ch * 32 + k2l) * 32 + c4);
                *(uint4*)&Bsl[k2l * 40 + c4] = *(const uint4*)(Pl + (ch * 32 + k2l) * 32 + c4);
            }
            __syncthreads();
#pragma unroll
            for (int kk2 = 0; kk2 < 32; kk2 += 8) {
                uint32_t ah[4], al[4];
                ah[0] = Ah[(m0 + gq) * 36 + kk2 + tq];
                ah[1] = Ah[(m0 + gq + 8) * 36 + kk2 + tq];
                ah[2] = Ah[(m0 + gq) * 36 + kk2 + tq + 4];
                ah[3] = Ah[(m0 + gq + 8) * 36 + kk2 + tq + 4];
                al[0] = Al[(m0 + gq) * 36 + kk2 + tq];
                al[1] = Al[(m0 + gq + 8) * 36 + kk2 + tq];
                al[2] = Al[(m0 + gq) * 36 + kk2 + tq + 4];
                al[3] = Al[(m0 + gq + 8) * 36 + kk2 + tq + 4];
#pragma unroll
                for (int na = 0; na < 2; ++na) {
                    int nc = (nb + na) * 8 + gq;
                    uint32_t bh0 = Bsh[(kk2 + tq) * 40 + nc];
                    uint32_t bh1 = Bsh[(kk2 + tq + 4) * 40 + nc];
                    uint32_t bl0 = Bsl[(kk2 + tq) * 40 + nc];
                    uint32_t bl1 = Bsl[(kk2 + tq + 4) * 40 + nc];
                    mma3b(acc[na], ah, al, bh0, bh1, bl0, bl1);
                }
            }
            __syncthreads();
        }
#pragma unroll
        for (int na = 0; na < 2; ++na) {
            int cc = col0 + (nb + na) * 8 + 2 * tq;
            int r = m0 + gq;
            __stcg((float2*)&g_pp[ks][r][cc],     make_float2(acc[na][0], acc[na][1]));
            __stcg((float2*)&g_pp[ks][r + 8][cc], make_float2(acc[na][2], acc[na][3]));
        }
    };

    auto softmax_row = [&](float* dst) {
        int b = bid;            // only blocks 0..63 call this
        float* row = Gs;        // 2112 floats >= 1024
        float lm = -1e30f;
        for (int o = tid; o < 1024; o += 256) {
            float v = __ldcg(&g_pp[0][b][o]) + __ldcg(&g_pp[1][b][o])
                    + __ldcg(&g_pp[2][b][o]) + __ldcg(&g_pp[3][b][o])
                    + __ldg(&b_out[o]);
            row[o] = v;
            lm = fmaxf(lm, v);
        }
#pragma unroll
        for (int s = 16; s; s >>= 1) lm = fmaxf(lm, __shfl_xor_sync(0xffffffffu, lm, s));
        if (lane == 0) red[wid] = lm;
        __syncthreads();
        if (tid == 0) {
            float mm = red[0];
#pragma unroll
            for (int i = 1; i < 8; ++i) mm = fmaxf(mm, red[i]);
            red[0] = mm;
        }
        __syncthreads();
        float mm = red[0];
        float s = 0.f;
        for (int o = tid; o < 1024; o += 256) s += expf(row[o] - mm);
#pragma unroll
        for (int sh = 16; sh; sh >>= 1) s += __shfl_xor_sync(0xffffffffu, s, sh);
        if (lane == 0) red[wid] = s;
        __syncthreads();
        if (tid == 0) {
            float tot = 0.f;
#pragma unroll
            for (int i = 0; i < 8; ++i) tot += red[i];
            *plse = mm + logf(tot);
        }
        __syncthreads();
        float lse = *plse;
        for (int o = tid; o < 1024; o += 256) __stcg(&dst[o], row[o] - lse);
        __syncthreads();
    };

    // ================= encode: 128 steps =================
    for (int t = 0; t < S_LEN; ++t) {
        float acc[2][4] = {};
        cell_pass_smemW(hb[t & 1], acc);
        cell_epilogue(acc, hb[(t + 1) & 1],
                      g_XgP + ((size_t)bid * S_LEN + t) * 2048);
        grid_sync();
    }

    // ================= first projection + softmax =================
    proj_pass(hb[0]);
    grid_sync();
    if (bid < 64) softmax_row(out + (size_t)bid * 1024);
    grid_sync();

    // ================= autoregressive decode =================
    const uint32_t* PihH = g_PihH + (size_t)bid * 16384;
    const uint32_t* PihL = g_PihL + (size_t)bid * 16384;
    for (int d = 1; d < T_OUT; ++d) {
        int s = S_LEN + d - 1;
        const float* x = out + (size_t)(d - 1) * ROW64;
        float acc[2][4] = {};
        cell_pass_smemW(hb[s & 1], acc);
        cell_pass_streamW(x, PihH, PihL, acc);
        cell_epilogue(acc, hb[(s + 1) & 1], nullptr);
        grid_sync();
        proj_pass(hb[(s + 1) & 1]);
        grid_sync();
        if (bid < 64) softmax_row(out + (size_t)d * ROW64 + (size_t)bid * 1024);
        grid_sync();
    }

    // ================= final h, c =================
    float* oc = out + (size_t)T_OUT * ROW64;
#pragma unroll
    for (int p = 0; p < 2; ++p) {
        int idx = tid + p * 256;
        int m = idx >> 3, jj = idx & 7;
        int off = m * 1024 + j0 + jj;
        oc[off] = __ldcg(hb[1] + off);
        oc[ROW64 + off] = g_c[off];
    }
}

// ---------------- host orchestration -----------------------------------------
extern "C" void kernel_launch(void* const* d_in, const int* in_sizes, int n_in,
                              void* d_out, int out_size) {
    const float* input = (const float*)d_in[0];
    const float* h0    = (const float*)d_in[1];
    const float* c0    = (const float*)d_in[2];
    const float* W_ih  = (const float*)d_in[3];
    const float* W_hh  = (const float*)d_in[4];
    const float* b_ih  = (const float*)d_in[5];
    const float* b_hh  = (const float*)d_in[6];
    const float* W_out = (const float*)d_in[7];
    const float* b_out = (const float*)d_in[8];
    float* out = (float*)d_out;

    uint32_t *p_PhhH, *p_PhhL, *p_PihH, *p_PihL;
    cudaGetSymbolAddress((void**)&p_PhhH, g_PhhH);
    cudaGetSymbolAddress((void**)&p_PhhL, g_PhhL);
    cudaGetSymbolAddress((void**)&p_PihH, g_PihH);
    cudaGetSymbolAddress((void**)&p_PihL, g_PihL);

    cudaFuncSetAttribute(lstm_persistent,
                         cudaFuncAttributeMaxDynamicSharedMemorySize, SMEM_BYTES);

    dim3 tb(32, 8);
    pack_cell_w<<<dim3(32, NBLK), tb>>>(W_hh, p_PhhH, p_PhhL);
    pack_cell_w<<<dim3(32, NBLK), tb>>>(W_ih, p_PihH, p_PihL);
    pack_big_w<<<dim3(32, 128), tb>>>(W_ih);
    pack_out_w<<<dim3(8, NBLK), tb>>>(W_out);
    prep_state_kernel<<<(ROW64 + 255) / 256, 256>>>(h0, c0, b_ih, b_hh);

    // XgP = input @ WihT (bf16x2 mma), written pre-packed per (block, t)
    gemm_xg_bf16<<<dim3(G4 / 64, (S_LEN * B_SZ) / 128), 256>>>(input);

    // the whole recurrence + decode in ONE persistent kernel
    lstm_persistent<<<NBLK, 256, SMEM_BYTES>>>(out, b_out);
}